// round 16
// baseline (speedup 1.0000x reference)
#include <cuda_runtime.h>
#include <cuda_fp16.h>
#include <cstdint>

#define NB 16384
#define ND 5000
#define NJ 192
#define KENC_PAD 5056          // 79 * 64
#define NDEC_PAD 5120          // 20 * 256
#define DEC_SCALE 0.0159f
#define CARD_B 24
#define CARD_C 10
#define NBIN (CARD_B * CARD_B + CARD_C * CARD_C)   // 676
#define BINCAP 512
#define NPE 3792               // pack_enc blocks: 192*5056/256
#define NPD 3840               // pack_dec blocks: 5120*192/256

// ---------------- device-global scratch --------------------------------------
__device__ __align__(16) __half g_Hh[NB * NJ];
__device__ __align__(16) __half g_WencH[NJ * KENC_PAD];
__device__ __align__(16) __half g_WdTH[NDEC_PAD * NJ];
__device__ __align__(16) float  g_MbT[CARD_B * CARD_B * 4096];
__device__ __align__(16) float  g_McT[CARD_C * CARD_C * 4096];
__device__ int g_cnt[NBIN];
__device__ int g_rows[NBIN * BINCAP];

// ---------------- PTX helpers -------------------------------------------------
__device__ __forceinline__ uint32_t s2u(const void* p) {
    return (uint32_t)__cvta_generic_to_shared(p);
}
__device__ __forceinline__ void cp16(uint32_t dst, const void* src) {
    asm volatile("cp.async.cg.shared.global [%0], [%1], 16;" :: "r"(dst), "l"(src));
}
__device__ __forceinline__ void cp_commit() {
    asm volatile("cp.async.commit_group;" ::: "memory");
}
template <int N> __device__ __forceinline__ void cp_wait() {
    asm volatile("cp.async.wait_group %0;" :: "n"(N) : "memory");
}
__device__ __forceinline__ void sts128(uint32_t a, uint32_t x, uint32_t y,
                                       uint32_t z, uint32_t w) {
    asm volatile("st.shared.v4.b32 [%0], {%1,%2,%3,%4};"
                 :: "r"(a), "r"(x), "r"(y), "r"(z), "r"(w) : "memory");
}
__device__ __forceinline__ void ldsm4(uint32_t* r, uint32_t a) {
    asm volatile("ldmatrix.sync.aligned.m8n8.x4.shared.b16 {%0,%1,%2,%3}, [%4];"
                 : "=r"(r[0]), "=r"(r[1]), "=r"(r[2]), "=r"(r[3]) : "r"(a));
}
__device__ __forceinline__ void mma16816(float* c, const uint32_t* a, const uint32_t* b) {
    asm volatile("mma.sync.aligned.m16n8k16.row.col.f32.f16.f16.f32 "
                 "{%0,%1,%2,%3},{%4,%5,%6,%7},{%8,%9},{%0,%1,%2,%3};"
                 : "+f"(c[0]), "+f"(c[1]), "+f"(c[2]), "+f"(c[3])
                 : "r"(a[0]), "r"(a[1]), "r"(a[2]), "r"(a[3]), "r"(b[0]), "r"(b[1]));
}
__device__ __forceinline__ uint32_t pack2h(float f0, float f1) {
    __half2 h = __floats2half2_rn(f0, f1);
    return *(uint32_t*)&h;
}

// ---------------- prep_a: pack_enc | pack_dec | composite | zero g_cnt ---------
__global__ __launch_bounds__(256) void prep_a_kernel(const float* __restrict__ Wb,
                                                     const float* __restrict__ Web,
                                                     const float* __restrict__ Wec,
                                                     const float* __restrict__ Wdb,
                                                     const float* __restrict__ Wdc,
                                                     const float* __restrict__ Whb,
                                                     const float* __restrict__ Whc) {
    const int bid = blockIdx.x;
    const int tid = threadIdx.x;

    if (bid < NPE) {                                  // ---- pack_enc
        int idx = bid * 256 + tid;
        int j = idx / KENC_PAD, d = idx - j * KENC_PAD;
        float v = 0.f;
        if (d < ND) {
            if (j < 64)       v = Wb[j * ND + d];
            else if (j < 128) v = Web[(j - 64) * ND + d];
            else              v = Wec[(j - 128) * ND + d];
        }
        g_WencH[idx] = __float2half_rn(v);
        return;
    }
    if (bid < NPE + NPD) {                            // ---- pack_dec
        int idx = (bid - NPE) * 256 + tid;
        int n = idx / NJ, j = idx - n * NJ;
        float v = 0.f;
        if (n < ND) {
            if (j < 64)       v = Wb[j * ND + n];
            else if (j < 128) v = Wdb[n * 64 + (j - 64)];
            else              v = Wdc[n * 64 + (j - 128)];
        }
        g_WdTH[idx] = __float2half_rn(v);
        return;
    }
    if (bid < NPE + NPD + NBIN) {                     // ---- composite
        __shared__ float sT[4096], sS[4096];
        int pair = bid - NPE - NPD;
        const float *Wt, *Ws;
        float* out;
        if (pair < CARD_B * CARD_B) {
            Wt = Whb + (size_t)(pair / CARD_B) * 4096;
            Ws = Whb + (size_t)(pair % CARD_B) * 4096;
            out = g_MbT + (size_t)pair * 4096;
        } else {
            int p = pair - CARD_B * CARD_B;
            Wt = Whc + (size_t)(p / CARD_C) * 4096;
            Ws = Whc + (size_t)(p % CARD_C) * 4096;
            out = g_McT + (size_t)p * 4096;
        }
        for (int i = tid; i < 4096; i += 256) { sT[i] = Wt[i]; sS[i] = Ws[i]; }
        __syncthreads();
        int m = tid >> 2, n0 = (tid & 3) * 16;
        float c[16];
#pragma unroll
        for (int j = 0; j < 16; j++) c[j] = 0.f;
        for (int l = 0; l < 64; l++) {
            float a = sT[m * 64 + l];
#pragma unroll
            for (int j = 0; j < 16; j++) c[j] = fmaf(a, sS[l * 64 + n0 + j], c[j]);
        }
#pragma unroll
        for (int j = 0; j < 16; j++) out[(n0 + j) * 64 + m] = c[j] * DEC_SCALE;
        return;
    }
    // ---- zero g_cnt (one block)
    for (int i = tid; i < NBIN; i += 256) g_cnt[i] = 0;
}

// ---------------- scatter: parallel bucket fill (capacity bins) ----------------
__global__ __launch_bounds__(256) void scatter_kernel(const int* __restrict__ sb,
                                                      const int* __restrict__ tb,
                                                      const int* __restrict__ sc,
                                                      const int* __restrict__ tc) {
    int row = blockIdx.x * 256 + threadIdx.x;
    if (row >= NB) return;
    int pb = tb[row] * CARD_B + sb[row];
    int pc = CARD_B * CARD_B + tc[row] * CARD_C + sc[row];
    int ib = atomicAdd(&g_cnt[pb], 1);
    if (ib < BINCAP) g_rows[pb * BINCAP + ib] = row;
    int ic = atomicAdd(&g_cnt[pc], 1);
    if (ic < BINCAP) g_rows[pc * BINCAP + ic] = row;
}

// ---------------- encode: single-pass fp16, BK=64 (frozen mainloop) ------------
// 512 threads, 16 warps 4Mx4N (warp 32x48). Tile 128x192.
// Stage (bytes, stride 51200): A0@0 | A1@10240 | B0@20480 | B1@35840
#define ENC_SMEM_BYTES (2 * 51200)
__global__ __launch_bounds__(512, 1) void encode_kernel(const float* __restrict__ A) {
    extern __shared__ __half sm[];
    const uint32_t sbase = s2u(sm);
    const int tid = threadIdx.x, wid = tid >> 5, lane = tid & 31;
    const int row0 = blockIdx.x * 128;
    const int wm = (wid & 3) * 32, wn = (wid >> 2) * 48;

    float acc[2][6][4];
#pragma unroll
    for (int i = 0; i < 2; i++)
#pragma unroll
        for (int j = 0; j < 6; j++)
#pragma unroll
            for (int k = 0; k < 4; k++) acc[i][j][k] = 0.f;

    float4 av[4];
    const int r_a = tid >> 2, c_a = tid & 3;
    auto ldgA = [&](int kt) {
        const int kg = kt * 64 + c_a * 16;
        const float* p = A + (size_t)(row0 + r_a) * ND + kg;
#pragma unroll
        for (int i = 0; i < 4; i++) {
            int k = kg + i * 4;
            av[i] = (k + 4 <= ND) ? *(const float4*)(p + i * 4)
                                  : make_float4(0.f, 0.f, 0.f, 0.f);
        }
    };
    auto stsA = [&](int s) {
        uint32_t base = sbase + (uint32_t)s * 51200u;
        const int sub = c_a >> 1;
        uint32_t o = (uint32_t)sub * 10240u +
                     (uint32_t)(r_a * 40 + (c_a & 1) * 16) * 2u;
        sts128(base + o, pack2h(av[0].x, av[0].y), pack2h(av[0].z, av[0].w),
                         pack2h(av[1].x, av[1].y), pack2h(av[1].z, av[1].w));
        sts128(base + o + 16u, pack2h(av[2].x, av[2].y), pack2h(av[2].z, av[2].w),
                               pack2h(av[3].x, av[3].y), pack2h(av[3].z, av[3].w));
    };
    auto cpB = [&](int kt, int s) {
        const int k0 = kt * 64;
        uint32_t base = sbase + (uint32_t)s * 51200u + 20480u;
#pragma unroll
        for (int u = 0; u < 3; u++) {
            int i = tid + u * 512;
            int n = i >> 3, c = i & 7;
            int sub = c >> 2, c4 = c & 3;
            uint32_t o = (uint32_t)sub * 15360u + (uint32_t)(n * 40 + c4 * 8) * 2u;
            cp16(base + o, g_WencH + (size_t)n * KENC_PAD + k0 + c * 8);
        }
    };

    const int NT = KENC_PAD / 64;   // 79
    ldgA(0);
    cpB(0, 0);
    cp_commit();
#pragma unroll 1
    for (int kt = 0; kt < NT; kt++) {
        const int s = kt & 1;
        stsA(s);
        cp_wait<0>();
        __syncthreads();
        if (kt + 1 < NT) {
            ldgA(kt + 1);
            cpB(kt + 1, s ^ 1);
            cp_commit();
        }
        const uint32_t base = sbase + (uint32_t)s * 51200u;
#pragma unroll
        for (int ks = 0; ks < 4; ks++) {
            const uint32_t abase = base + (uint32_t)(ks >> 1) * 10240u;
            const uint32_t bbase = base + 20480u + (uint32_t)(ks >> 1) * 15360u;
            const int kk = (ks & 1) * 16;
            uint32_t ah[2][4];
#pragma unroll
            for (int mt = 0; mt < 2; mt++) {
                uint32_t o = (uint32_t)((wm + mt * 16 + (lane & 15)) * 40 +
                                        kk + (lane >> 4) * 8) * 2u;
                ldsm4(ah[mt], abase + o);
            }
            uint32_t bh[3][4];
#pragma unroll
            for (int pr = 0; pr < 3; pr++) {
                int n = wn + pr * 16 + (lane & 7) + ((lane >> 4) & 1) * 8;
                uint32_t o = (uint32_t)(n * 40 + kk + ((lane >> 3) & 1) * 8) * 2u;
                ldsm4(bh[pr], bbase + o);
            }
#pragma unroll
            for (int mt = 0; mt < 2; mt++)
#pragma unroll
                for (int nt = 0; nt < 6; nt++)
                    mma16816(acc[mt][nt], ah[mt], &bh[nt >> 1][(nt & 1) * 2]);
        }
    }

    // epilogue: ALL cols -> fp16 g_Hh (heads reads fp16; decode reads fp16)
#pragma unroll
    for (int mt = 0; mt < 2; mt++) {
        int r = row0 + wm + mt * 16 + (lane >> 2);
#pragma unroll
        for (int nt = 0; nt < 6; nt++) {
            int cg = wn + nt * 8 + (lane & 3) * 2;
#pragma unroll
            for (int half = 0; half < 2; half++) {
                int rr = r + half * 8;
                *(uint32_t*)(g_Hh + (size_t)rr * NJ + cg) =
                    pack2h(acc[mt][nt][half * 2], acc[mt][nt][half * 2 + 1]);
            }
        }
    }
}

// ---------------- heads: one CTA per context pair (fp16 in/out) ----------------
__global__ __launch_bounds__(256) void heads_kernel() {
    __shared__ float Ms[4096];
    const int pair = blockIdx.x;
    const int tid = threadIdx.x, wid = tid >> 5, lane = tid & 31;
    const float* M = (pair < CARD_B * CARD_B)
                         ? g_MbT + (size_t)pair * 4096
                         : g_McT + (size_t)(pair - CARD_B * CARD_B) * 4096;
    const int colbase = (pair < CARD_B * CARD_B) ? 64 : 128;
    for (int i = tid; i < 4096; i += 256) Ms[i] = M[i];
    __syncthreads();
    const int cnt = min(g_cnt[pair], BINCAP);
    const int* rows = g_rows + (size_t)pair * BINCAP;
    for (int i = wid; i < cnt; i += 8) {
        int row = rows[i];
        __half2 xh = ((const __half2*)(g_Hh + (size_t)row * NJ + colbase))[lane];
        float2 x = __half22float2(xh);
        float y0 = 0.f, y1 = 0.f;
#pragma unroll
        for (int li = 0; li < 32; li++) {
            float vx = __shfl_sync(0xffffffffu, x.x, li);
            float vy = __shfl_sync(0xffffffffu, x.y, li);
            int l0 = li * 2;
            y0 = fmaf(vx, Ms[l0 * 64 + lane], y0);
            y1 = fmaf(vx, Ms[l0 * 64 + 32 + lane], y1);
            y0 = fmaf(vy, Ms[(l0 + 1) * 64 + lane], y0);
            y1 = fmaf(vy, Ms[(l0 + 1) * 64 + 32 + lane], y1);
        }
        size_t o = (size_t)row * NJ + colbase;
        g_Hh[o + lane]      = __float2half_rn(y0);
        g_Hh[o + 32 + lane] = __float2half_rn(y1);
    }
}

// ---------------- decode: persistent col-panel, 64x64 warp tiles (frozen) ------
// grid (20, 7) = 140 CTAs. CTA tile 128 rows x 256 cols, 8 warps 2Mx4N.
// smem: B@0 (102400) | A stage s @ 102400 + s*51200 ; total 204800.
#define DEC_SMEM_BYTES (102400 + 2 * 51200)
__global__ __launch_bounds__(256, 1) void decode_kernel(float* __restrict__ out) {
    extern __shared__ __half sm[];
    const uint32_t sbase = s2u(sm);
    const int tid = threadIdx.x, wid = tid >> 5, lane = tid & 31;
    const int col0 = blockIdx.x * 256;
    const int rowg = blockIdx.y;
    const int start = rowg * 18 + min(rowg, 2);
    const int count = (rowg < 2) ? 19 : 18;           // 2*19 + 5*18 = 128
    const int wm = (wid & 1) * 64, wn = (wid >> 1) * 64;

    for (int i = tid; i < 6144; i += 256) {           // B panel 256 cols x 24 chunks
        int n = i / 24, c = i - n * 24;
        uint32_t o = (uint32_t)(n * 200 + c * 8) * 2u;
        cp16(sbase + o, g_WdTH + (size_t)(col0 + n) * NJ + c * 8);
    }

    uint32_t a_off[12];
    int a_rel[12];
#pragma unroll
    for (int u = 0; u < 12; u++) {
        int i = tid + u * 256;
        int r = i / 24, c = i - r * 24;
        a_off[u] = (uint32_t)(r * 200 + c * 8) * 2u;
        a_rel[u] = r * NJ + c * 8;
    }
    auto cpA = [&](int tile, int s) {
        uint32_t base = sbase + 102400u + (uint32_t)s * 51200u;
        size_t g0 = (size_t)tile * 128 * NJ;
#pragma unroll
        for (int u = 0; u < 12; u++)
            cp16(base + a_off[u], g_Hh + g0 + a_rel[u]);
    };

    cpA(start, 0);
    cp_commit();

    float acc[4][8][4];
#pragma unroll 1
    for (int t = 0; t < count; t++) {
        const int s = t & 1;
        cp_wait<0>();
        __syncthreads();
        if (t + 1 < count) {
            cpA(start + t + 1, s ^ 1);
            cp_commit();
        }

#pragma unroll
        for (int i = 0; i < 4; i++)
#pragma unroll
            for (int j = 0; j < 8; j++)
#pragma unroll
                for (int k = 0; k < 4; k++) acc[i][j][k] = 0.f;

        const uint32_t abase = sbase + 102400u + (uint32_t)s * 51200u;
#pragma unroll 1
        for (int ks = 0; ks < 12; ks++) {
            const int kk = ks * 16;
            uint32_t ah[4][4];
#pragma unroll
            for (int mt = 0; mt < 4; mt++) {
                uint32_t o = (uint32_t)((wm + mt * 16 + (lane & 15)) * 200 +
                                        kk + (lane >> 4) * 8) * 2u;
                ldsm4(ah[mt], abase + o);
            }
            uint32_t bh[4][4];
#pragma unroll
            for (int pr = 0; pr < 4; pr++) {
                int n = wn + pr * 16 + (lane & 7) + ((lane >> 4) & 1) * 8;
                uint32_t o = (uint32_t)(n * 200 + kk + ((lane >> 3) & 1) * 8) * 2u;
                ldsm4(bh[pr], sbase + o);
            }
#pragma unroll
            for (int mt = 0; mt < 4; mt++)
#pragma unroll
                for (int nt = 0; nt < 8; nt++)
                    mma16816(acc[mt][nt], ah[mt], &bh[nt >> 1][(nt & 1) * 2]);
        }

        const int trow0 = (start + t) * 128;
#pragma unroll
        for (int mt = 0; mt < 4; mt++) {
            int r = trow0 + wm + mt * 16 + (lane >> 2);
#pragma unroll
            for (int nt = 0; nt < 8; nt++) {
                int cg = col0 + wn + nt * 8 + (lane & 3) * 2;
                if (cg < ND) {
                    *(float2*)(out + (size_t)r * ND + cg) =
                        make_float2(acc[mt][nt][0], acc[mt][nt][1]);
                    *(float2*)(out + (size_t)(r + 8) * ND + cg) =
                        make_float2(acc[mt][nt][2], acc[mt][nt][3]);
                }
            }
        }
    }
}

// ---------------- launch --------------------------------------------------------
extern "C" void kernel_launch(void* const* d_in, const int* in_sizes, int n_in,
                              void* d_out, int out_size) {
    const float* expr = (const float*)d_in[0];
    const int* sb = (const int*)d_in[1];
    const int* tb = (const int*)d_in[2];
    const int* sc = (const int*)d_in[3];
    const int* tc = (const int*)d_in[4];
    const float* Wb  = (const float*)d_in[5];
    const float* Web = (const float*)d_in[6];
    const float* Wdb = (const float*)d_in[7];
    const float* Whb = (const float*)d_in[8];
    const float* Wec = (const float*)d_in[9];
    const float* Wdc = (const float*)d_in[10];
    const float* Whc = (const float*)d_in[11];
    float* out = (float*)d_out;

    cudaFuncSetAttribute(encode_kernel, cudaFuncAttributeMaxDynamicSharedMemorySize,
                         ENC_SMEM_BYTES);
    cudaFuncSetAttribute(decode_kernel, cudaFuncAttributeMaxDynamicSharedMemorySize,
                         DEC_SMEM_BYTES);

    // 5 launches; #4 (the one ncu captures) is heads_kernel.
    prep_a_kernel<<<NPE + NPD + NBIN + 1, 256>>>(Wb, Web, Wec, Wdb, Wdc, Whb, Whc);
    encode_kernel<<<NB / 128, 512, ENC_SMEM_BYTES>>>(expr);
    scatter_kernel<<<NB / 256, 256>>>(sb, tb, sc, tc);
    heads_kernel<<<NBIN, 256>>>();
    decode_kernel<<<dim3(20, 7), 256, DEC_SMEM_BYTES>>>(out);
}

// round 17
// speedup vs baseline: 1.0409x; 1.0409x over previous
#include <cuda_runtime.h>
#include <cuda_fp16.h>
#include <cstdint>

#define NB 16384
#define ND 5000
#define NJ 192
#define KENC_PAD 5056          // 79 * 64
#define NDEC_PAD 5120          // 20 * 256
#define DEC_SCALE 0.0159f
#define CARD_B 24
#define CARD_C 10
#define NBIN (CARD_B * CARD_B + CARD_C * CARD_C)   // 676
#define BINCAP 512
#define NPE 3792               // pack_enc blocks: 192*5056/256
#define NPD 3840               // pack_dec blocks: 5120*192/256

// ---------------- device-global scratch --------------------------------------
__device__ __align__(16) __half g_Hh[NB * NJ];
__device__ __align__(16) __half g_WencH[NJ * KENC_PAD];
__device__ __align__(16) __half g_WdTH[NDEC_PAD * NJ];
__device__ __align__(16) float  g_MbT[CARD_B * CARD_B * 4096];
__device__ __align__(16) float  g_McT[CARD_C * CARD_C * 4096];
__device__ int g_cnt[NBIN];
__device__ int g_rows[NBIN * BINCAP];

// ---------------- PTX helpers -------------------------------------------------
__device__ __forceinline__ uint32_t s2u(const void* p) {
    return (uint32_t)__cvta_generic_to_shared(p);
}
__device__ __forceinline__ void cp16(uint32_t dst, const void* src) {
    asm volatile("cp.async.cg.shared.global [%0], [%1], 16;" :: "r"(dst), "l"(src));
}
__device__ __forceinline__ void cp_commit() {
    asm volatile("cp.async.commit_group;" ::: "memory");
}
template <int N> __device__ __forceinline__ void cp_wait() {
    asm volatile("cp.async.wait_group %0;" :: "n"(N) : "memory");
}
__device__ __forceinline__ void sts128(uint32_t a, uint32_t x, uint32_t y,
                                       uint32_t z, uint32_t w) {
    asm volatile("st.shared.v4.b32 [%0], {%1,%2,%3,%4};"
                 :: "r"(a), "r"(x), "r"(y), "r"(z), "r"(w) : "memory");
}
__device__ __forceinline__ void ldsm4(uint32_t* r, uint32_t a) {
    asm volatile("ldmatrix.sync.aligned.m8n8.x4.shared.b16 {%0,%1,%2,%3}, [%4];"
                 : "=r"(r[0]), "=r"(r[1]), "=r"(r[2]), "=r"(r[3]) : "r"(a));
}
__device__ __forceinline__ void mma16816(float* c, const uint32_t* a, const uint32_t* b) {
    asm volatile("mma.sync.aligned.m16n8k16.row.col.f32.f16.f16.f32 "
                 "{%0,%1,%2,%3},{%4,%5,%6,%7},{%8,%9},{%0,%1,%2,%3};"
                 : "+f"(c[0]), "+f"(c[1]), "+f"(c[2]), "+f"(c[3])
                 : "r"(a[0]), "r"(a[1]), "r"(a[2]), "r"(a[3]), "r"(b[0]), "r"(b[1]));
}
__device__ __forceinline__ uint32_t pack2h(float f0, float f1) {
    __half2 h = __floats2half2_rn(f0, f1);
    return *(uint32_t*)&h;
}

// ---------------- prep_a: pack_enc | pack_dec | composite | zero g_cnt ---------
__global__ __launch_bounds__(256) void prep_a_kernel(const float* __restrict__ Wb,
                                                     const float* __restrict__ Web,
                                                     const float* __restrict__ Wec,
                                                     const float* __restrict__ Wdb,
                                                     const float* __restrict__ Wdc,
                                                     const float* __restrict__ Whb,
                                                     const float* __restrict__ Whc) {
    const int bid = blockIdx.x;
    const int tid = threadIdx.x;

    if (bid < NPE) {                                  // ---- pack_enc
        int idx = bid * 256 + tid;
        int j = idx / KENC_PAD, d = idx - j * KENC_PAD;
        float v = 0.f;
        if (d < ND) {
            if (j < 64)       v = Wb[j * ND + d];
            else if (j < 128) v = Web[(j - 64) * ND + d];
            else              v = Wec[(j - 128) * ND + d];
        }
        g_WencH[idx] = __float2half_rn(v);
        return;
    }
    if (bid < NPE + NPD) {                            // ---- pack_dec
        int idx = (bid - NPE) * 256 + tid;
        int n = idx / NJ, j = idx - n * NJ;
        float v = 0.f;
        if (n < ND) {
            if (j < 64)       v = Wb[j * ND + n];
            else if (j < 128) v = Wdb[n * 64 + (j - 64)];
            else              v = Wdc[n * 64 + (j - 128)];
        }
        g_WdTH[idx] = __float2half_rn(v);
        return;
    }
    if (bid < NPE + NPD + NBIN) {                     // ---- composite
        __shared__ float sT[4096], sS[4096];
        int pair = bid - NPE - NPD;
        const float *Wt, *Ws;
        float* out;
        if (pair < CARD_B * CARD_B) {
            Wt = Whb + (size_t)(pair / CARD_B) * 4096;
            Ws = Whb + (size_t)(pair % CARD_B) * 4096;
            out = g_MbT + (size_t)pair * 4096;
        } else {
            int p = pair - CARD_B * CARD_B;
            Wt = Whc + (size_t)(p / CARD_C) * 4096;
            Ws = Whc + (size_t)(p % CARD_C) * 4096;
            out = g_McT + (size_t)p * 4096;
        }
        for (int i = tid; i < 4096; i += 256) { sT[i] = Wt[i]; sS[i] = Ws[i]; }
        __syncthreads();
        int m = tid >> 2, n0 = (tid & 3) * 16;
        float c[16];
#pragma unroll
        for (int j = 0; j < 16; j++) c[j] = 0.f;
        for (int l = 0; l < 64; l++) {
            float a = sT[m * 64 + l];
#pragma unroll
            for (int j = 0; j < 16; j++) c[j] = fmaf(a, sS[l * 64 + n0 + j], c[j]);
        }
#pragma unroll
        for (int j = 0; j < 16; j++) out[(n0 + j) * 64 + m] = c[j] * DEC_SCALE;
        return;
    }
    // ---- zero g_cnt (one block)
    for (int i = tid; i < NBIN; i += 256) g_cnt[i] = 0;
}

// ---------------- scatter: parallel bucket fill (capacity bins) ----------------
__global__ __launch_bounds__(256) void scatter_kernel(const int* __restrict__ sb,
                                                      const int* __restrict__ tb,
                                                      const int* __restrict__ sc,
                                                      const int* __restrict__ tc) {
    int row = blockIdx.x * 256 + threadIdx.x;
    if (row >= NB) return;
    int pb = tb[row] * CARD_B + sb[row];
    int pc = CARD_B * CARD_B + tc[row] * CARD_C + sc[row];
    int ib = atomicAdd(&g_cnt[pb], 1);
    if (ib < BINCAP) g_rows[pb * BINCAP + ib] = row;
    int ic = atomicAdd(&g_cnt[pc], 1);
    if (ic < BINCAP) g_rows[pc * BINCAP + ic] = row;
}

// ---------------- encode: single-pass fp16, BK=64 (frozen mainloop) ------------
// 512 threads, 16 warps 4Mx4N (warp 32x48). Tile 128x192.
// Stage (bytes, stride 51200): A0@0 | A1@10240 | B0@20480 | B1@35840
#define ENC_SMEM_BYTES (2 * 51200)
__global__ __launch_bounds__(512, 1) void encode_kernel(const float* __restrict__ A) {
    extern __shared__ __half sm[];
    const uint32_t sbase = s2u(sm);
    const int tid = threadIdx.x, wid = tid >> 5, lane = tid & 31;
    const int row0 = blockIdx.x * 128;
    const int wm = (wid & 3) * 32, wn = (wid >> 2) * 48;

    float acc[2][6][4];
#pragma unroll
    for (int i = 0; i < 2; i++)
#pragma unroll
        for (int j = 0; j < 6; j++)
#pragma unroll
            for (int k = 0; k < 4; k++) acc[i][j][k] = 0.f;

    float4 av[4];
    const int r_a = tid >> 2, c_a = tid & 3;
    auto ldgA = [&](int kt) {
        const int kg = kt * 64 + c_a * 16;
        const float* p = A + (size_t)(row0 + r_a) * ND + kg;
#pragma unroll
        for (int i = 0; i < 4; i++) {
            int k = kg + i * 4;
            av[i] = (k + 4 <= ND) ? *(const float4*)(p + i * 4)
                                  : make_float4(0.f, 0.f, 0.f, 0.f);
        }
    };
    auto stsA = [&](int s) {
        uint32_t base = sbase + (uint32_t)s * 51200u;
        const int sub = c_a >> 1;
        uint32_t o = (uint32_t)sub * 10240u +
                     (uint32_t)(r_a * 40 + (c_a & 1) * 16) * 2u;
        sts128(base + o, pack2h(av[0].x, av[0].y), pack2h(av[0].z, av[0].w),
                         pack2h(av[1].x, av[1].y), pack2h(av[1].z, av[1].w));
        sts128(base + o + 16u, pack2h(av[2].x, av[2].y), pack2h(av[2].z, av[2].w),
                               pack2h(av[3].x, av[3].y), pack2h(av[3].z, av[3].w));
    };
    auto cpB = [&](int kt, int s) {
        const int k0 = kt * 64;
        uint32_t base = sbase + (uint32_t)s * 51200u + 20480u;
#pragma unroll
        for (int u = 0; u < 3; u++) {
            int i = tid + u * 512;
            int n = i >> 3, c = i & 7;
            int sub = c >> 2, c4 = c & 3;
            uint32_t o = (uint32_t)sub * 15360u + (uint32_t)(n * 40 + c4 * 8) * 2u;
            cp16(base + o, g_WencH + (size_t)n * KENC_PAD + k0 + c * 8);
        }
    };

    const int NT = KENC_PAD / 64;   // 79
    ldgA(0);
    cpB(0, 0);
    cp_commit();
#pragma unroll 1
    for (int kt = 0; kt < NT; kt++) {
        const int s = kt & 1;
        stsA(s);
        cp_wait<0>();
        __syncthreads();
        if (kt + 1 < NT) {
            ldgA(kt + 1);
            cpB(kt + 1, s ^ 1);
            cp_commit();
        }
        const uint32_t base = sbase + (uint32_t)s * 51200u;
#pragma unroll
        for (int ks = 0; ks < 4; ks++) {
            const uint32_t abase = base + (uint32_t)(ks >> 1) * 10240u;
            const uint32_t bbase = base + 20480u + (uint32_t)(ks >> 1) * 15360u;
            const int kk = (ks & 1) * 16;
            uint32_t ah[2][4];
#pragma unroll
            for (int mt = 0; mt < 2; mt++) {
                uint32_t o = (uint32_t)((wm + mt * 16 + (lane & 15)) * 40 +
                                        kk + (lane >> 4) * 8) * 2u;
                ldsm4(ah[mt], abase + o);
            }
            uint32_t bh[3][4];
#pragma unroll
            for (int pr = 0; pr < 3; pr++) {
                int n = wn + pr * 16 + (lane & 7) + ((lane >> 4) & 1) * 8;
                uint32_t o = (uint32_t)(n * 40 + kk + ((lane >> 3) & 1) * 8) * 2u;
                ldsm4(bh[pr], bbase + o);
            }
#pragma unroll
            for (int mt = 0; mt < 2; mt++)
#pragma unroll
                for (int nt = 0; nt < 6; nt++)
                    mma16816(acc[mt][nt], ah[mt], &bh[nt >> 1][(nt & 1) * 2]);
        }
    }

    // epilogue: ALL cols -> fp16 g_Hh
#pragma unroll
    for (int mt = 0; mt < 2; mt++) {
        int r = row0 + wm + mt * 16 + (lane >> 2);
#pragma unroll
        for (int nt = 0; nt < 6; nt++) {
            int cg = wn + nt * 8 + (lane & 3) * 2;
#pragma unroll
            for (int half = 0; half < 2; half++) {
                int rr = r + half * 8;
                *(uint32_t*)(g_Hh + (size_t)rr * NJ + cg) =
                    pack2h(acc[mt][nt][half * 2], acc[mt][nt][half * 2 + 1]);
            }
        }
    }
}

// ---------------- heads: 4-row ILP per warp, 2 blocks per bin ------------------
__global__ __launch_bounds__(256) void heads_kernel() {
    __shared__ float Ms[4096];
    const int pair = blockIdx.x >> 1;
    const int halfb = blockIdx.x & 1;
    const int tid = threadIdx.x, wid = tid >> 5, lane = tid & 31;
    const float* M = (pair < CARD_B * CARD_B)
                         ? g_MbT + (size_t)pair * 4096
                         : g_McT + (size_t)(pair - CARD_B * CARD_B) * 4096;
    const int colbase = (pair < CARD_B * CARD_B) ? 64 : 128;
    for (int i = tid; i < 4096; i += 256) Ms[i] = M[i];
    __syncthreads();
    const int cnt_all = min(g_cnt[pair], BINCAP);
    const int h0 = (cnt_all + 1) >> 1;                // split bin in two halves
    const int lo = halfb ? h0 : 0;
    const int hi = halfb ? cnt_all : h0;
    const int* rows = g_rows + (size_t)pair * BINCAP;

    for (int i0 = lo + wid * 4; i0 < hi; i0 += 32) {
        const int nr = min(4, hi - i0);
        int row[4];
        float2 x[4];
#pragma unroll
        for (int r = 0; r < 4; r++) {
            if (r < nr) {
                row[r] = rows[i0 + r];
                x[r] = __half22float2(
                    ((const __half2*)(g_Hh + (size_t)row[r] * NJ + colbase))[lane]);
            } else {
                x[r] = make_float2(0.f, 0.f);
            }
        }
        float y0[4] = {0.f, 0.f, 0.f, 0.f};
        float y1[4] = {0.f, 0.f, 0.f, 0.f};
#pragma unroll
        for (int li = 0; li < 32; li++) {
            const int l0 = li * 2;
            const float m00 = Ms[l0 * 64 + lane];
            const float m01 = Ms[l0 * 64 + 32 + lane];
            const float m10 = Ms[(l0 + 1) * 64 + lane];
            const float m11 = Ms[(l0 + 1) * 64 + 32 + lane];
#pragma unroll
            for (int r = 0; r < 4; r++) {
                float vx = __shfl_sync(0xffffffffu, x[r].x, li);
                float vy = __shfl_sync(0xffffffffu, x[r].y, li);
                y0[r] = fmaf(vx, m00, y0[r]);
                y1[r] = fmaf(vx, m01, y1[r]);
                y0[r] = fmaf(vy, m10, y0[r]);
                y1[r] = fmaf(vy, m11, y1[r]);
            }
        }
#pragma unroll
        for (int r = 0; r < 4; r++) {
            if (r < nr) {
                size_t o = (size_t)row[r] * NJ + colbase;
                g_Hh[o + lane]      = __float2half_rn(y0[r]);
                g_Hh[o + 32 + lane] = __float2half_rn(y1[r]);
            }
        }
    }
}

// ---------------- decode: persistent col-panel, 64x64 warp tiles (frozen) ------
// grid (20, 7) = 140 CTAs. CTA tile 128 rows x 256 cols, 8 warps 2Mx4N.
// smem: B@0 (102400) | A stage s @ 102400 + s*51200 ; total 204800.
#define DEC_SMEM_BYTES (102400 + 2 * 51200)
__global__ __launch_bounds__(256, 1) void decode_kernel(float* __restrict__ out) {
    extern __shared__ __half sm[];
    const uint32_t sbase = s2u(sm);
    const int tid = threadIdx.x, wid = tid >> 5, lane = tid & 31;
    const int col0 = blockIdx.x * 256;
    const int rowg = blockIdx.y;
    const int start = rowg * 18 + min(rowg, 2);
    const int count = (rowg < 2) ? 19 : 18;           // 2*19 + 5*18 = 128
    const int wm = (wid & 1) * 64, wn = (wid >> 1) * 64;

    for (int i = tid; i < 6144; i += 256) {           // B panel 256 cols x 24 chunks
        int n = i / 24, c = i - n * 24;
        uint32_t o = (uint32_t)(n * 200 + c * 8) * 2u;
        cp16(sbase + o, g_WdTH + (size_t)(col0 + n) * NJ + c * 8);
    }

    uint32_t a_off[12];
    int a_rel[12];
#pragma unroll
    for (int u = 0; u < 12; u++) {
        int i = tid + u * 256;
        int r = i / 24, c = i - r * 24;
        a_off[u] = (uint32_t)(r * 200 + c * 8) * 2u;
        a_rel[u] = r * NJ + c * 8;
    }
    auto cpA = [&](int tile, int s) {
        uint32_t base = sbase + 102400u + (uint32_t)s * 51200u;
        size_t g0 = (size_t)tile * 128 * NJ;
#pragma unroll
        for (int u = 0; u < 12; u++)
            cp16(base + a_off[u], g_Hh + g0 + a_rel[u]);
    };

    cpA(start, 0);
    cp_commit();

    float acc[4][8][4];
#pragma unroll 1
    for (int t = 0; t < count; t++) {
        const int s = t & 1;
        cp_wait<0>();
        __syncthreads();
        if (t + 1 < count) {
            cpA(start + t + 1, s ^ 1);
            cp_commit();
        }

#pragma unroll
        for (int i = 0; i < 4; i++)
#pragma unroll
            for (int j = 0; j < 8; j++)
#pragma unroll
                for (int k = 0; k < 4; k++) acc[i][j][k] = 0.f;

        const uint32_t abase = sbase + 102400u + (uint32_t)s * 51200u;
#pragma unroll 1
        for (int ks = 0; ks < 12; ks++) {
            const int kk = ks * 16;
            uint32_t ah[4][4];
#pragma unroll
            for (int mt = 0; mt < 4; mt++) {
                uint32_t o = (uint32_t)((wm + mt * 16 + (lane & 15)) * 200 +
                                        kk + (lane >> 4) * 8) * 2u;
                ldsm4(ah[mt], abase + o);
            }
            uint32_t bh[4][4];
#pragma unroll
            for (int pr = 0; pr < 4; pr++) {
                int n = wn + pr * 16 + (lane & 7) + ((lane >> 4) & 1) * 8;
                uint32_t o = (uint32_t)(n * 200 + kk + ((lane >> 3) & 1) * 8) * 2u;
                ldsm4(bh[pr], sbase + o);
            }
#pragma unroll
            for (int mt = 0; mt < 4; mt++)
#pragma unroll
                for (int nt = 0; nt < 8; nt++)
                    mma16816(acc[mt][nt], ah[mt], &bh[nt >> 1][(nt & 1) * 2]);
        }

        const int trow0 = (start + t) * 128;
#pragma unroll
        for (int mt = 0; mt < 4; mt++) {
            int r = trow0 + wm + mt * 16 + (lane >> 2);
#pragma unroll
            for (int nt = 0; nt < 8; nt++) {
                int cg = col0 + wn + nt * 8 + (lane & 3) * 2;
                if (cg < ND) {
                    *(float2*)(out + (size_t)r * ND + cg) =
                        make_float2(acc[mt][nt][0], acc[mt][nt][1]);
                    *(float2*)(out + (size_t)(r + 8) * ND + cg) =
                        make_float2(acc[mt][nt][2], acc[mt][nt][3]);
                }
            }
        }
    }
}

// ---------------- launch --------------------------------------------------------
extern "C" void kernel_launch(void* const* d_in, const int* in_sizes, int n_in,
                              void* d_out, int out_size) {
    const float* expr = (const float*)d_in[0];
    const int* sb = (const int*)d_in[1];
    const int* tb = (const int*)d_in[2];
    const int* sc = (const int*)d_in[3];
    const int* tc = (const int*)d_in[4];
    const float* Wb  = (const float*)d_in[5];
    const float* Web = (const float*)d_in[6];
    const float* Wdb = (const float*)d_in[7];
    const float* Whb = (const float*)d_in[8];
    const float* Wec = (const float*)d_in[9];
    const float* Wdc = (const float*)d_in[10];
    const float* Whc = (const float*)d_in[11];
    float* out = (float*)d_out;

    cudaFuncSetAttribute(encode_kernel, cudaFuncAttributeMaxDynamicSharedMemorySize,
                         ENC_SMEM_BYTES);
    cudaFuncSetAttribute(decode_kernel, cudaFuncAttributeMaxDynamicSharedMemorySize,
                         DEC_SMEM_BYTES);

    // 5 launches; #4 (the one ncu captures) is heads_kernel.
    prep_a_kernel<<<NPE + NPD + NBIN + 1, 256>>>(Wb, Web, Wec, Wdb, Wdc, Whb, Whc);
    encode_kernel<<<NB / 128, 512, ENC_SMEM_BYTES>>>(expr);
    scatter_kernel<<<NB / 256, 256>>>(sb, tb, sc, tc);
    heads_kernel<<<NBIN * 2, 256>>>();
    decode_kernel<<<dim3(20, 7), 256, DEC_SMEM_BYTES>>>(out);
}